// round 15
// baseline (speedup 1.0000x reference)
#include <cuda_runtime.h>
#include <cuda_fp16.h>
#include <math.h>
#include <stdint.h>

#define TT   4096
#define EE   8
#define HH   1024
#define DFFC 2048
#define PP   (TT*2)

// ---------------- device scratch ----------------
__device__ int      g_cnt[EE];
__device__ int      g_base[EE];
__device__ int      g_tok[EE][TT];
__device__ float    g_wt [EE][TT];
__device__ unsigned g_ticket = 0;

__device__ __half g_xq[TT*HH];
__device__ __half g_gq[EE*DFFC*HH];
__device__ __half g_uq[EE*DFFC*HH];
__device__ __half g_dq[EE*HH*DFFC];
__device__ __half g_iq[(size_t)PP*DFFC];

// ---------------- helpers ----------------
__device__ __forceinline__ uint32_t s2u(const void* p) {
    return (uint32_t)__cvta_generic_to_shared(p);
}
__device__ __forceinline__ void cp16(uint32_t dst, const void* src) {
    asm volatile("cp.async.cg.shared.global [%0], [%1], 16;" :: "r"(dst), "l"(src) : "memory");
}
// mbarrier primitives
__device__ __forceinline__ void mbar_init(uint32_t mb, uint32_t cnt) {
    asm volatile("mbarrier.init.shared.b64 [%0], %1;" :: "r"(mb), "r"(cnt) : "memory");
}
// arrive (consuming one expected arrival) once ALL this thread's prior cp.async landed.
// .noinc is ESSENTIAL (R11 hang without it).
__device__ __forceinline__ void cp_arrive(uint32_t mb) {
    asm volatile("cp.async.mbarrier.arrive.noinc.shared.b64 [%0];" :: "r"(mb) : "memory");
}
__device__ __forceinline__ void mbar_arrive(uint32_t mb) {
    asm volatile("mbarrier.arrive.shared.b64 _, [%0];" :: "r"(mb) : "memory");
}
__device__ __forceinline__ void mbar_wait(uint32_t mb, uint32_t parity) {
    asm volatile("{\n\t.reg .pred P;\n\t"
                 "W%=:\n\t"
                 "mbarrier.try_wait.parity.shared.b64 P, [%0], %1;\n\t"
                 "@P bra.uni D%=;\n\t"
                 "bra.uni W%=;\n\t"
                 "D%=:\n\t}"
                 :: "r"(mb), "r"(parity) : "memory");
}

__device__ __forceinline__ void ldsm4(unsigned &r0, unsigned &r1, unsigned &r2, unsigned &r3,
                                      unsigned addr) {
    asm volatile("ldmatrix.sync.aligned.m8n8.x4.shared.b16 {%0,%1,%2,%3}, [%4];"
                 : "=r"(r0), "=r"(r1), "=r"(r2), "=r"(r3) : "r"(addr));
}
__device__ __forceinline__ void mma16816(float c[4], const unsigned a[4],
                                         unsigned b0, unsigned b1) {
    asm volatile("mma.sync.aligned.m16n8k16.row.col.f32.f16.f16.f32 "
                 "{%0,%1,%2,%3}, {%4,%5,%6,%7}, {%8,%9}, {%0,%1,%2,%3};"
                 : "+f"(c[0]), "+f"(c[1]), "+f"(c[2]), "+f"(c[3])
                 : "r"(a[0]), "r"(a[1]), "r"(a[2]), "r"(a[3]), "r"(b0), "r"(b1));
}
// 16x16 A fragment at (m0, k=ks*16), smem tile row stride 80B
__device__ __forceinline__ void ldfragA(unsigned f[4], unsigned base, int m0, int ks, int lane) {
    int sub = lane >> 3;
    int r   = m0 + (lane & 7) + ((sub & 1) << 3);
    int kg  = (ks << 1) + (sub >> 1);
    ldsm4(f[0], f[1], f[2], f[3], base + r * 80 + (kg << 4));
}
// B fragments for 2 adjacent n8 tiles (n0..n0+15) at k=ks*16
__device__ __forceinline__ void ldfragB(unsigned f[4], unsigned base, int n0, int ks, int lane) {
    int sub = lane >> 3;
    int r   = n0 + (lane & 7) + ((sub >> 1) << 3);
    int kg  = (ks << 1) + (sub & 1);
    ldsm4(f[0], f[1], f[2], f[3], base + r * 80 + (kg << 4));
}
__device__ __forceinline__ void red2(float* p, float x, float y) {
    asm volatile("red.global.add.v2.f32 [%0], {%1,%2};" :: "l"(p), "f"(x), "f"(y) : "memory");
}

// ---------------- kernel: convert all weights/x + zero out + reset counters -
#define NG4 (EE*DFFC*HH/4)
#define NX4 (TT*HH/4)
#define NZ4 (TT*HH/4)
__global__ void k_conv(const float4* __restrict__ gw, const float4* __restrict__ uw,
                       const float4* __restrict__ dw, const float4* __restrict__ x,
                       float4* __restrict__ out) {
    int i = blockIdx.x * blockDim.x + threadIdx.x;
    if (i < EE) g_cnt[i] = 0;
    if (i < NZ4) out[i] = make_float4(0.f, 0.f, 0.f, 0.f);

    const float4* src; __half* dst; int idx; bool stream;
    if      (i < NG4)           { src = gw; dst = g_gq; idx = i;          stream = true; }
    else if (i < 2*NG4)         { src = uw; dst = g_uq; idx = i - NG4;    stream = true; }
    else if (i < 3*NG4)         { src = dw; dst = g_dq; idx = i - 2*NG4;  stream = true; }
    else if (i < 3*NG4 + NX4)   { src = x;  dst = g_xq; idx = i - 3*NG4;  stream = false; }
    else return;

    float4 v = stream ? __ldcs(src + idx) : src[idx];
    __half2 h0 = __floats2half2_rn(v.x, v.y);
    __half2 h1 = __floats2half2_rn(v.z, v.w);
    if (stream) {
        __stcs((__half2*)dst + 2*idx,     h0);
        __stcs((__half2*)dst + 2*idx + 1, h1);
    } else {
        ((__half2*)dst)[2*idx]     = h0;
        ((__half2*)dst)[2*idx + 1] = h1;
    }
}

// ---------------- kernel: router (+ fused prefix/counts via ticket) ---------
__global__ void k_router(const float* __restrict__ x, const float* __restrict__ cent,
                         const float* __restrict__ bias,
                         float* __restrict__ out, int write_counts) {
    int warp = threadIdx.x >> 5, lane = threadIdx.x & 31;
    int t = blockIdx.x * 8 + warp;
    const float* xr = x + (size_t)t * HH;
    float acc[EE];
#pragma unroll
    for (int e = 0; e < EE; e++) acc[e] = 0.f;
    for (int h = lane; h < HH; h += 32) {
        float xv = xr[h];
#pragma unroll
        for (int e = 0; e < EE; e++) acc[e] += xv * cent[e * HH + h];
    }
#pragma unroll
    for (int e = 0; e < EE; e++)
#pragma unroll
        for (int o = 16; o > 0; o >>= 1)
            acc[e] += __shfl_down_sync(0xffffffffu, acc[e], o);
    if (lane == 0) {
        float s[EE];
#pragma unroll
        for (int e = 0; e < EE; e++)
            s[e] = 1.f / (1.f + expf(-acc[e])) + bias[e];
        float v0 = -1e30f; int i0 = 0;
#pragma unroll
        for (int e = 0; e < EE; e++) if (s[e] > v0) { v0 = s[e]; i0 = e; }
        float v1 = -1e30f; int i1 = 0;
#pragma unroll
        for (int e = 0; e < EE; e++) if (e != i0 && s[e] > v1) { v1 = s[e]; i1 = e; }
        float e1 = expf(v1 - v0);
        float w0 = 1.f / (1.f + e1), w1 = e1 * w0;
        int s0 = atomicAdd(&g_cnt[i0], 1);
        g_tok[i0][s0] = t; g_wt[i0][s0] = w0;
        int s1 = atomicAdd(&g_cnt[i1], 1);
        g_tok[i1][s1] = t; g_wt[i1][s1] = w1;
    }

    __syncthreads();
    if (threadIdx.x == 0) {
        __threadfence();
        unsigned tk = atomicAdd(&g_ticket, 1);
        if (tk == gridDim.x - 1) {
            g_ticket = 0;
            int b = 0;
#pragma unroll
            for (int e = 0; e < EE; e++) {
                g_base[e] = b;
                int c = g_cnt[e];
                b += c;
                if (write_counts) out[(size_t)TT * HH + e] = (float)c;
            }
        }
    }
}

// ============ gate/up grouped GEMM + fused SwiGLU (B-prefetch consume) ======
// CTA: 64 tokens x 64 dff (gate & up), BK=32, 128 thr, warps 2x2 (m32 n32).
#define GU_TILE  5120                 // 64 rows * 80B
#define GU_STAGE (3*GU_TILE)          // A G U
#define GU_NS    3
__global__ __launch_bounds__(128) void k_gateup_mma() {
    int e   = blockIdx.z;
    int cnt = g_cnt[e];
    int r0  = blockIdx.y * 64;
    if (r0 >= cnt) return;
    int n0  = blockIdx.x * 64;

    extern __shared__ __align__(128) char smx[];
    __shared__ int toks[64];
    __shared__ __align__(8) uint64_t s_full[GU_NS], s_empty[GU_NS];

    int tid = threadIdx.x, lane = tid & 31, warp = tid >> 5;
    if (tid == 0) {
#pragma unroll
        for (int s = 0; s < GU_NS; s++) { mbar_init(s2u(&s_full[s]), 128); mbar_init(s2u(&s_empty[s]), 4); }
    }
    if (tid < 64) toks[tid] = (r0 + tid < cnt) ? g_tok[e][r0 + tid] : g_tok[e][0];
    __syncthreads();

    uint32_t sbase = s2u(smx);
    uint32_t mbf = s2u(&s_full[0]), mbe = s2u(&s_empty[0]);
    int row0 = tid >> 2, kg = tid & 3;

    const char* px = (const char*)g_xq;
    const char* pg = (const char*)g_gq;
    const char* pu = (const char*)g_uq;

    uint32_t a0 = (uint32_t)toks[row0]      * (HH*2) + kg*16;
    uint32_t a1 = (uint32_t)toks[row0 + 32] * (HH*2) + kg*16;
    uint32_t wofs = (uint32_t)(e * DFFC + n0) * (HH*2);
    uint32_t w0 = wofs + (uint32_t)row0        * (HH*2) + kg*16;
    uint32_t w1 = wofs + (uint32_t)(row0 + 32) * (HH*2) + kg*16;
    uint32_t so0 = row0 * 80 + kg * 16, so1 = so0 + 2560;

    auto issue = [&](int kt, int slot) {
        uint32_t sb = sbase + slot * GU_STAGE;
        uint32_t kb = (uint32_t)kt * 64;
        cp16(sb             + so0, px + a0 + kb); cp16(sb             + so1, px + a1 + kb);
        cp16(sb +   GU_TILE + so0, pg + w0 + kb); cp16(sb +   GU_TILE + so1, pg + w1 + kb);
        cp16(sb + 2*GU_TILE + so0, pu + w0 + kb); cp16(sb + 2*GU_TILE + so1, pu + w1 + kb);
    };

    issue(0, 0); cp_arrive(mbf);
    issue(1, 1); cp_arrive(mbf + 8);

    int wm = warp >> 1, wn = warp & 1;
    int m0 = wm * 32, nb = wn * 32;

    float cg[2][4][4], cu[2][4][4];
#pragma unroll
    for (int a = 0; a < 2; a++)
#pragma unroll
        for (int b = 0; b < 4; b++)
#pragma unroll
            for (int c = 0; c < 4; c++) { cg[a][b][c] = 0.f; cu[a][b][c] = 0.f; }

    // B-fragment-only double buffering (pressure-light: +4 regs vs R12).
    // Per ks: A frags loaded once; B sequence G@nb, G@nb+16, U@nb, U@nb+16
    // prefetched one ahead -> 3 of 4 ldsm->mma RAWs hidden per ks.
    auto consume = [&](int slot) {
        uint32_t sb = sbase + slot * GU_STAGE;
        uint32_t sA = sb, sG = sb + GU_TILE, sU = sb + 2*GU_TILE;
#pragma unroll
        for (int ks = 0; ks < 2; ks++) {
            unsigned ah0[4], ah1[4], f[2][4];
            ldfragA(ah0, sA, m0,      ks, lane);
            ldfragA(ah1, sA, m0 + 16, ks, lane);
            ldfragB(f[0], sG, nb, ks, lane);
#pragma unroll
            for (int it = 0; it < 4; it++) {
                if (it + 1 < 4) {
                    int nit = it + 1;
                    ldfragB(f[nit & 1], (nit < 2) ? sG : sU, nb + (nit & 1) * 16, ks, lane);
                }
                unsigned* fh = f[it & 1];
                int j = (it & 1) * 2;
                if (it < 2) {
                    mma16816(cg[0][j],   ah0, fh[0], fh[1]);
                    mma16816(cg[0][j+1], ah0, fh[2], fh[3]);
                    mma16816(cg[1][j],   ah1, fh[0], fh[1]);
                    mma16816(cg[1][j+1], ah1, fh[2], fh[3]);
                } else {
                    mma16816(cu[0][j],   ah0, fh[0], fh[1]);
                    mma16816(cu[0][j+1], ah0, fh[2], fh[3]);
                    mma16816(cu[1][j],   ah1, fh[0], fh[1]);
                    mma16816(cu[1][j+1], ah1, fh[2], fh[3]);
                }
            }
        }
    };

    const int NT = HH / 32;   // 32
    uint32_t fullP = 0, emptyP = 0;
    int sc = 0, sp = 2;
    for (int kt = 0; kt < NT; kt++) {
        int nx = kt + 2;
        if (nx < NT) {
            if (nx >= GU_NS) {                       // WAR: slot reused
                mbar_wait(mbe + sp*8, (emptyP >> sp) & 1);
                emptyP ^= (1u << sp);
            }
            issue(nx, sp);
            cp_arrive(mbf + sp*8);
        }
        mbar_wait(mbf + sc*8, (fullP >> sc) & 1);    // RAW: stage data ready
        fullP ^= (1u << sc);
        consume(sc);
        if (lane == 0) mbar_arrive(mbe + sc*8);      // per-warp release
        sc = (sc == GU_NS-1) ? 0 : sc + 1;
        sp = (sp == GU_NS-1) ? 0 : sp + 1;
    }

    // epilogue: SwiGLU in fp32 registers (fast exp), store fp16 intermediate
    int pb = g_base[e] + r0;
#pragma unroll
    for (int mi = 0; mi < 2; mi++)
#pragma unroll
        for (int half = 0; half < 2; half++) {
            int rl = m0 + mi*16 + (lane >> 2) + half*8;
            if (r0 + rl < cnt) {
                size_t p = (size_t)(pb + rl);
#pragma unroll
                for (int j = 0; j < 4; j++) {
                    int col = n0 + nb + j*8 + (lane & 3)*2;
                    float g0 = cg[mi][j][half*2+0], g1 = cg[mi][j][half*2+1];
                    float u0 = cu[mi][j][half*2+0], u1 = cu[mi][j][half*2+1];
                    float h0 = (g0 / (1.f + __expf(-g0))) * u0;
                    float h1 = (g1 / (1.f + __expf(-g1))) * u1;
                    *(__half2*)(g_iq + p * DFFC + col) = __floats2half2_rn(h0, h1);
                }
            }
        }
}

// ============ down grouped GEMM + weighted scatter (R13 prefetch consume) ===
// CTA: 64 pairs x 128 H, BK=32, 128 thr. Warp (2x2): m32 x n64. 3-slot ring.
#define DN_ATILE 5120                 // 64 * 80
#define DN_BTILE 10240                // 128 * 80
#define DN_STAGE (DN_ATILE + DN_BTILE)   // 15360
#define DN_NS    3
__global__ __launch_bounds__(128) void k_down_mma(float* __restrict__ out) {
    int e   = blockIdx.z;
    int cnt = g_cnt[e];
    int r0  = blockIdx.y * 64;
    if (r0 >= cnt) return;
    int n0  = blockIdx.x * 128;

    extern __shared__ __align__(128) char smx[];
    __shared__ int   toks[64];
    __shared__ float ws[64];
    __shared__ int   prows[64];
    __shared__ __align__(8) uint64_t s_full[DN_NS], s_empty[DN_NS];

    int tid = threadIdx.x, lane = tid & 31, warp = tid >> 5;
    if (tid == 0) {
#pragma unroll
        for (int s = 0; s < DN_NS; s++) { mbar_init(s2u(&s_full[s]), 128); mbar_init(s2u(&s_empty[s]), 4); }
    }
    if (tid < 64) {
        bool ok = (r0 + tid) < cnt;
        toks[tid]  = ok ? g_tok[e][r0 + tid] : 0;
        ws[tid]    = ok ? g_wt [e][r0 + tid] : 0.f;
        prows[tid] = ok ? (g_base[e] + r0 + tid) : g_base[e];
    }
    __syncthreads();

    uint32_t sbase = s2u(smx);
    uint32_t mbf = s2u(&s_full[0]), mbe = s2u(&s_empty[0]);
    int row0 = tid >> 2, kg = tid & 3;

    const char* pi = (const char*)g_iq;
    const char* pd = (const char*)g_dq;

    uint32_t a0 = (uint32_t)prows[row0]      * (DFFC*2) + kg*16;
    uint32_t a1 = (uint32_t)prows[row0 + 32] * (DFFC*2) + kg*16;
    uint32_t wofs = (uint32_t)(e * HH + n0) * (DFFC*2);
    uint32_t b0 = wofs + (uint32_t)row0        * (DFFC*2) + kg*16;
    uint32_t b1 = wofs + (uint32_t)(row0 + 32) * (DFFC*2) + kg*16;
    uint32_t b2 = wofs + (uint32_t)(row0 + 64) * (DFFC*2) + kg*16;
    uint32_t b3 = wofs + (uint32_t)(row0 + 96) * (DFFC*2) + kg*16;
    uint32_t so0 = row0 * 80 + kg * 16;

    auto issue = [&](int kt, int slot) {
        uint32_t sb = sbase + slot * DN_STAGE;
        uint32_t kb = (uint32_t)kt * 64;
        uint32_t sA = sb, sB = sb + DN_ATILE;
        cp16(sA + so0,        pi + a0 + kb); cp16(sA + so0 + 2560, pi + a1 + kb);
        cp16(sB + so0,        pd + b0 + kb); cp16(sB + so0 + 2560, pd + b1 + kb);
        cp16(sB + so0 + 5120, pd + b2 + kb); cp16(sB + so0 + 7680, pd + b3 + kb);
    };

    issue(0, 0); cp_arrive(mbf);
    issue(1, 1); cp_arrive(mbf + 8);

    int wm = warp >> 1, wn = warp & 1;
    int m0 = wm * 32, nb = wn * 64;

    float c[2][8][4];
#pragma unroll
    for (int a = 0; a < 2; a++)
#pragma unroll
        for (int b = 0; b < 8; b++)
#pragma unroll
            for (int k = 0; k < 4; k++) c[a][b][k] = 0.f;

    // R13 prefetch consume (measured win for down): it = ks*4 + ng
    auto consume = [&](int slot) {
        uint32_t sb = sbase + slot * DN_STAGE;
        uint32_t sA = sb, sB = sb + DN_ATILE;
        unsigned ac0[4], ac1[4], an0[4], an1[4], f[2][4];
        ldfragA(ac0, sA, m0,      0, lane);
        ldfragA(ac1, sA, m0 + 16, 0, lane);
        ldfragB(f[0], sB, nb, 0, lane);
#pragma unroll
        for (int it = 0; it < 8; it++) {
            int ks = it >> 2, ng = it & 3;
            if (it + 1 < 8) {
                int nit = it + 1;
                ldfragB(f[nit & 1], sB, nb + (nit & 3) * 16, nit >> 2, lane);
            }
            if (it == 1) {
                ldfragA(an0, sA, m0,      1, lane);
                ldfragA(an1, sA, m0 + 16, 1, lane);
            }
            unsigned* fh = f[it & 1];
            if (ks == 0) {
                mma16816(c[0][2*ng],   ac0, fh[0], fh[1]);
                mma16816(c[0][2*ng+1], ac0, fh[2], fh[3]);
                mma16816(c[1][2*ng],   ac1, fh[0], fh[1]);
                mma16816(c[1][2*ng+1], ac1, fh[2], fh[3]);
            } else {
                mma16816(c[0][2*ng],   an0, fh[0], fh[1]);
                mma16816(c[0][2*ng+1], an0, fh[2], fh[3]);
                mma16816(c[1][2*ng],   an1, fh[0], fh[1]);
                mma16816(c[1][2*ng+1], an1, fh[2], fh[3]);
            }
        }
    };

    const int NT = DFFC / 32;   // 64
    uint32_t fullP = 0, emptyP = 0;
    int sc = 0, sp = 2;
    for (int kt = 0; kt < NT; kt++) {
        int nx = kt + 2;
        if (nx < NT) {
            if (nx >= DN_NS) {
                mbar_wait(mbe + sp*8, (emptyP >> sp) & 1);
                emptyP ^= (1u << sp);
            }
            issue(nx, sp);
            cp_arrive(mbf + sp*8);
        }
        mbar_wait(mbf + sc*8, (fullP >> sc) & 1);
        fullP ^= (1u << sc);
        consume(sc);
        if (lane == 0) mbar_arrive(mbe + sc*8);
        sc = (sc == DN_NS-1) ? 0 : sc + 1;
        sp = (sp == DN_NS-1) ? 0 : sp + 1;
    }

    // epilogue: weighted vector-atomic scatter
#pragma unroll
    for (int mi = 0; mi < 2; mi++)
#pragma unroll
        for (int half = 0; half < 2; half++) {
            int rl = m0 + mi*16 + (lane >> 2) + half*8;
            if (r0 + rl < cnt) {
                int   t = toks[rl];
                float w = ws[rl];
                float* dst = out + (size_t)t * HH;
#pragma unroll
                for (int j = 0; j < 8; j++) {
                    int col = n0 + nb + j*8 + (lane & 3)*2;
                    red2(dst + col, w * c[mi][j][half*2+0], w * c[mi][j][half*2+1]);
                }
            }
        }
}

// ---------------- launch ----------------
extern "C" void kernel_launch(void* const* d_in, const int* in_sizes, int n_in,
                              void* d_out, int out_size) {
    const float* x    = (const float*)d_in[0];
    const float* cent = (const float*)d_in[1];
    const float* gw   = (const float*)d_in[2];
    const float* uw   = (const float*)d_in[3];
    const float* dw   = (const float*)d_in[4];
    const float* bias = (const float*)d_in[5];
    float* out = (float*)d_out;

    int write_counts = (out_size >= TT * HH + EE) ? 1 : 0;
    int nconv = 3 * NG4 + NX4;

    cudaFuncSetAttribute(k_gateup_mma, cudaFuncAttributeMaxDynamicSharedMemorySize,
                         GU_NS * GU_STAGE);
    cudaFuncSetAttribute(k_down_mma, cudaFuncAttributeMaxDynamicSharedMemorySize,
                         DN_NS * DN_STAGE);

    k_conv<<<(nconv + 255) / 256, 256>>>((const float4*)gw, (const float4*)uw,
                                         (const float4*)dw, (const float4*)x,
                                         (float4*)out);
    k_router<<<TT / 8, 256>>>(x, cent, bias, out, write_counts);
    k_gateup_mma<<<dim3(DFFC / 64, TT / 64, EE), 128, GU_NS * GU_STAGE>>>();
    k_down_mma  <<<dim3(HH / 128, TT / 64, EE), 128, DN_NS * DN_STAGE>>>(out);
}

// round 16
// speedup vs baseline: 1.0042x; 1.0042x over previous
#include <cuda_runtime.h>
#include <cuda_fp16.h>
#include <math.h>
#include <stdint.h>

#define TT   4096
#define EE   8
#define HH   1024
#define DFFC 2048
#define PP   (TT*2)

// ---------------- device scratch ----------------
__device__ int      g_cnt[EE];
__device__ int      g_base[EE];
__device__ int      g_tok[EE][TT];
__device__ float    g_wt [EE][TT];
__device__ unsigned g_ticket = 0;

__device__ __half g_xq[TT*HH];
__device__ __half g_gq[EE*DFFC*HH];
__device__ __half g_uq[EE*DFFC*HH];
__device__ __half g_dq[EE*HH*DFFC];
__device__ __half g_iq[(size_t)PP*DFFC];

// ---------------- helpers ----------------
__device__ __forceinline__ uint32_t s2u(const void* p) {
    return (uint32_t)__cvta_generic_to_shared(p);
}
__device__ __forceinline__ void cp16(uint32_t dst, const void* src) {
    asm volatile("cp.async.cg.shared.global [%0], [%1], 16;" :: "r"(dst), "l"(src) : "memory");
}
// mbarrier primitives
__device__ __forceinline__ void mbar_init(uint32_t mb, uint32_t cnt) {
    asm volatile("mbarrier.init.shared.b64 [%0], %1;" :: "r"(mb), "r"(cnt) : "memory");
}
// arrive (consuming one expected arrival) once ALL this thread's prior cp.async landed.
// .noinc is ESSENTIAL (R11 hang without it).
__device__ __forceinline__ void cp_arrive(uint32_t mb) {
    asm volatile("cp.async.mbarrier.arrive.noinc.shared.b64 [%0];" :: "r"(mb) : "memory");
}
__device__ __forceinline__ void mbar_arrive(uint32_t mb) {
    asm volatile("mbarrier.arrive.shared.b64 _, [%0];" :: "r"(mb) : "memory");
}
__device__ __forceinline__ void mbar_wait(uint32_t mb, uint32_t parity) {
    asm volatile("{\n\t.reg .pred P;\n\t"
                 "W%=:\n\t"
                 "mbarrier.try_wait.parity.shared.b64 P, [%0], %1;\n\t"
                 "@P bra.uni D%=;\n\t"
                 "bra.uni W%=;\n\t"
                 "D%=:\n\t}"
                 :: "r"(mb), "r"(parity) : "memory");
}

__device__ __forceinline__ void ldsm4(unsigned &r0, unsigned &r1, unsigned &r2, unsigned &r3,
                                      unsigned addr) {
    asm volatile("ldmatrix.sync.aligned.m8n8.x4.shared.b16 {%0,%1,%2,%3}, [%4];"
                 : "=r"(r0), "=r"(r1), "=r"(r2), "=r"(r3) : "r"(addr));
}
__device__ __forceinline__ void mma16816(float c[4], const unsigned a[4],
                                         unsigned b0, unsigned b1) {
    asm volatile("mma.sync.aligned.m16n8k16.row.col.f32.f16.f16.f32 "
                 "{%0,%1,%2,%3}, {%4,%5,%6,%7}, {%8,%9}, {%0,%1,%2,%3};"
                 : "+f"(c[0]), "+f"(c[1]), "+f"(c[2]), "+f"(c[3])
                 : "r"(a[0]), "r"(a[1]), "r"(a[2]), "r"(a[3]), "r"(b0), "r"(b1));
}
// 16x16 A fragment at (m0, k=ks*16), smem tile row stride 80B
__device__ __forceinline__ void ldfragA(unsigned f[4], unsigned base, int m0, int ks, int lane) {
    int sub = lane >> 3;
    int r   = m0 + (lane & 7) + ((sub & 1) << 3);
    int kg  = (ks << 1) + (sub >> 1);
    ldsm4(f[0], f[1], f[2], f[3], base + r * 80 + (kg << 4));
}
// B fragments for 2 adjacent n8 tiles (n0..n0+15) at k=ks*16
__device__ __forceinline__ void ldfragB(unsigned f[4], unsigned base, int n0, int ks, int lane) {
    int sub = lane >> 3;
    int r   = n0 + (lane & 7) + ((sub >> 1) << 3);
    int kg  = (ks << 1) + (sub & 1);
    ldsm4(f[0], f[1], f[2], f[3], base + r * 80 + (kg << 4));
}
__device__ __forceinline__ void red2(float* p, float x, float y) {
    asm volatile("red.global.add.v2.f32 [%0], {%1,%2};" :: "l"(p), "f"(x), "f"(y) : "memory");
}

// ---------------- kernel: convert all weights/x + zero out + reset counters -
#define NG4 (EE*DFFC*HH/4)
#define NX4 (TT*HH/4)
#define NZ4 (TT*HH/4)
__global__ void k_conv(const float4* __restrict__ gw, const float4* __restrict__ uw,
                       const float4* __restrict__ dw, const float4* __restrict__ x,
                       float4* __restrict__ out) {
    int i = blockIdx.x * blockDim.x + threadIdx.x;
    if (i < EE) g_cnt[i] = 0;
    if (i < NZ4) out[i] = make_float4(0.f, 0.f, 0.f, 0.f);

    const float4* src; __half* dst; int idx; bool stream;
    if      (i < NG4)           { src = gw; dst = g_gq; idx = i;          stream = true; }
    else if (i < 2*NG4)         { src = uw; dst = g_uq; idx = i - NG4;    stream = true; }
    else if (i < 3*NG4)         { src = dw; dst = g_dq; idx = i - 2*NG4;  stream = true; }
    else if (i < 3*NG4 + NX4)   { src = x;  dst = g_xq; idx = i - 3*NG4;  stream = false; }
    else return;

    float4 v = stream ? __ldcs(src + idx) : src[idx];
    __half2 h0 = __floats2half2_rn(v.x, v.y);
    __half2 h1 = __floats2half2_rn(v.z, v.w);
    if (stream) {
        __stcs((__half2*)dst + 2*idx,     h0);
        __stcs((__half2*)dst + 2*idx + 1, h1);
    } else {
        ((__half2*)dst)[2*idx]     = h0;
        ((__half2*)dst)[2*idx + 1] = h1;
    }
}

// ---------------- kernel: router (+ fused prefix/counts via ticket) ---------
__global__ void k_router(const float* __restrict__ x, const float* __restrict__ cent,
                         const float* __restrict__ bias,
                         float* __restrict__ out, int write_counts) {
    int warp = threadIdx.x >> 5, lane = threadIdx.x & 31;
    int t = blockIdx.x * 8 + warp;
    const float* xr = x + (size_t)t * HH;
    float acc[EE];
#pragma unroll
    for (int e = 0; e < EE; e++) acc[e] = 0.f;
    for (int h = lane; h < HH; h += 32) {
        float xv = xr[h];
#pragma unroll
        for (int e = 0; e < EE; e++) acc[e] += xv * cent[e * HH + h];
    }
#pragma unroll
    for (int e = 0; e < EE; e++)
#pragma unroll
        for (int o = 16; o > 0; o >>= 1)
            acc[e] += __shfl_down_sync(0xffffffffu, acc[e], o);
    if (lane == 0) {
        float s[EE];
#pragma unroll
        for (int e = 0; e < EE; e++)
            s[e] = 1.f / (1.f + expf(-acc[e])) + bias[e];
        float v0 = -1e30f; int i0 = 0;
#pragma unroll
        for (int e = 0; e < EE; e++) if (s[e] > v0) { v0 = s[e]; i0 = e; }
        float v1 = -1e30f; int i1 = 0;
#pragma unroll
        for (int e = 0; e < EE; e++) if (e != i0 && s[e] > v1) { v1 = s[e]; i1 = e; }
        float e1 = expf(v1 - v0);
        float w0 = 1.f / (1.f + e1), w1 = e1 * w0;
        int s0 = atomicAdd(&g_cnt[i0], 1);
        g_tok[i0][s0] = t; g_wt[i0][s0] = w0;
        int s1 = atomicAdd(&g_cnt[i1], 1);
        g_tok[i1][s1] = t; g_wt[i1][s1] = w1;
    }

    __syncthreads();
    if (threadIdx.x == 0) {
        __threadfence();
        unsigned tk = atomicAdd(&g_ticket, 1);
        if (tk == gridDim.x - 1) {
            g_ticket = 0;
            int b = 0;
#pragma unroll
            for (int e = 0; e < EE; e++) {
                g_base[e] = b;
                int c = g_cnt[e];
                b += c;
                if (write_counts) out[(size_t)TT * HH + e] = (float)c;
            }
        }
    }
}

// ============ gate/up grouped GEMM + fused SwiGLU (128-row CTA) ============
// CTA: 128 tokens x 64 dff, 256 thr, 8 warps (4m x 2n), warp m32 x n32.
// mbarrier ring: full=256 (cp.async.noinc), empty=8 (per-warp). R12 consume.
// 64 B/HMMA (vs 120 before) -> under the ~6.3KB/cyc LTS cap.
#define GUA_TILE (128*80)                 // 10240
#define GUB_TILE (64*80)                  // 5120
#define GU_STAGE (GUA_TILE + 2*GUB_TILE)  // 20480
#define GU_NS    3
__global__ __launch_bounds__(256) void k_gateup_mma() {
    int e   = blockIdx.z;
    int cnt = g_cnt[e];
    int r0  = blockIdx.y * 128;
    if (r0 >= cnt) return;
    int n0  = blockIdx.x * 64;

    extern __shared__ __align__(128) char smx[];
    __shared__ int toks[128];
    __shared__ __align__(8) uint64_t s_full[GU_NS], s_empty[GU_NS];

    int tid = threadIdx.x, lane = tid & 31, warp = tid >> 5;
    if (tid == 0) {
#pragma unroll
        for (int s = 0; s < GU_NS; s++) { mbar_init(s2u(&s_full[s]), 256); mbar_init(s2u(&s_empty[s]), 8); }
    }
    if (tid < 128) toks[tid] = (r0 + tid < cnt) ? g_tok[e][r0 + tid] : g_tok[e][0];
    __syncthreads();

    uint32_t sbase = s2u(smx);
    uint32_t mbf = s2u(&s_full[0]), mbe = s2u(&s_empty[0]);
    int lr = tid >> 2, kg = tid & 3;   // lr 0..63, kg 0..3

    const char* px = (const char*)g_xq;
    const char* pg = (const char*)g_gq;
    const char* pu = (const char*)g_uq;

    uint32_t a0 = (uint32_t)toks[lr]      * (HH*2) + kg*16;
    uint32_t a1 = (uint32_t)toks[lr + 64] * (HH*2) + kg*16;
    uint32_t wofs = (uint32_t)(e * DFFC + n0) * (HH*2);
    uint32_t w0 = wofs + (uint32_t)lr * (HH*2) + kg*16;
    uint32_t soA = lr * 80 + kg * 16;   // rows 0..63; row+64 at +5120

    auto issue = [&](int kt, int slot) {
        uint32_t sb = sbase + slot * GU_STAGE;
        uint32_t kb = (uint32_t)kt * 64;
        cp16(sb + soA,        px + a0 + kb);
        cp16(sb + soA + 5120, px + a1 + kb);
        cp16(sb + GUA_TILE            + soA, pg + w0 + kb);
        cp16(sb + GUA_TILE + GUB_TILE + soA, pu + w0 + kb);
    };

    issue(0, 0); cp_arrive(mbf);
    issue(1, 1); cp_arrive(mbf + 8);

    int wm = warp >> 1, wn = warp & 1;
    int m0 = wm * 32, nb = wn * 32;

    float cg[2][4][4], cu[2][4][4];
#pragma unroll
    for (int a = 0; a < 2; a++)
#pragma unroll
        for (int b = 0; b < 4; b++)
#pragma unroll
            for (int c = 0; c < 4; c++) { cg[a][b][c] = 0.f; cu[a][b][c] = 0.f; }

    // R12 simple consume (measured best for gateup; prefetch regressed twice)
    auto consume = [&](int slot) {
        uint32_t sb = sbase + slot * GU_STAGE;
        uint32_t sA = sb, sG = sb + GUA_TILE, sU = sb + GUA_TILE + GUB_TILE;
#pragma unroll
        for (int ks = 0; ks < 2; ks++) {
            unsigned ah0[4], ah1[4], fh[4];
            ldfragA(ah0, sA, m0,      ks, lane);
            ldfragA(ah1, sA, m0 + 16, ks, lane);
#pragma unroll
            for (int ng = 0; ng < 2; ng++) {
                ldfragB(fh, sG, nb + ng*16, ks, lane);
                mma16816(cg[0][2*ng],   ah0, fh[0], fh[1]);
                mma16816(cg[0][2*ng+1], ah0, fh[2], fh[3]);
                mma16816(cg[1][2*ng],   ah1, fh[0], fh[1]);
                mma16816(cg[1][2*ng+1], ah1, fh[2], fh[3]);
            }
#pragma unroll
            for (int ng = 0; ng < 2; ng++) {
                ldfragB(fh, sU, nb + ng*16, ks, lane);
                mma16816(cu[0][2*ng],   ah0, fh[0], fh[1]);
                mma16816(cu[0][2*ng+1], ah0, fh[2], fh[3]);
                mma16816(cu[1][2*ng],   ah1, fh[0], fh[1]);
                mma16816(cu[1][2*ng+1], ah1, fh[2], fh[3]);
            }
        }
    };

    const int NT = HH / 32;   // 32
    uint32_t fullP = 0, emptyP = 0;
    int sc = 0, sp = 2;
    for (int kt = 0; kt < NT; kt++) {
        int nx = kt + 2;
        if (nx < NT) {
            if (nx >= GU_NS) {                       // WAR: slot reused
                mbar_wait(mbe + sp*8, (emptyP >> sp) & 1);
                emptyP ^= (1u << sp);
            }
            issue(nx, sp);
            cp_arrive(mbf + sp*8);
        }
        mbar_wait(mbf + sc*8, (fullP >> sc) & 1);    // RAW: stage data ready
        fullP ^= (1u << sc);
        consume(sc);
        if (lane == 0) mbar_arrive(mbe + sc*8);      // per-warp release
        sc = (sc == GU_NS-1) ? 0 : sc + 1;
        sp = (sp == GU_NS-1) ? 0 : sp + 1;
    }

    // epilogue: SwiGLU in fp32 registers (fast exp), store fp16 intermediate
    int pb = g_base[e] + r0;
#pragma unroll
    for (int mi = 0; mi < 2; mi++)
#pragma unroll
        for (int half = 0; half < 2; half++) {
            int rl = m0 + mi*16 + (lane >> 2) + half*8;
            if (r0 + rl < cnt) {
                size_t p = (size_t)(pb + rl);
#pragma unroll
                for (int j = 0; j < 4; j++) {
                    int col = n0 + nb + j*8 + (lane & 3)*2;
                    float g0 = cg[mi][j][half*2+0], g1 = cg[mi][j][half*2+1];
                    float u0 = cu[mi][j][half*2+0], u1 = cu[mi][j][half*2+1];
                    float h0 = (g0 / (1.f + __expf(-g0))) * u0;
                    float h1 = (g1 / (1.f + __expf(-g1))) * u1;
                    *(__half2*)(g_iq + p * DFFC + col) = __floats2half2_rn(h0, h1);
                }
            }
        }
}

// ============ down grouped GEMM + weighted scatter (128-row CTA) ============
// CTA: 128 pairs x 128 H, 256 thr, 8 warps (4m x 2n), warp m32 x n64.
// mbarrier ring full=256/empty=8. R13 prefetch consume. 64 B/HMMA.
#define DNA_TILE (128*80)                 // 10240
#define DNB_TILE (128*80)                 // 10240
#define DN_STAGE (DNA_TILE + DNB_TILE)    // 20480
#define DN_NS    3
__global__ __launch_bounds__(256) void k_down_mma(float* __restrict__ out) {
    int e   = blockIdx.z;
    int cnt = g_cnt[e];
    int r0  = blockIdx.y * 128;
    if (r0 >= cnt) return;
    int n0  = blockIdx.x * 128;

    extern __shared__ __align__(128) char smx[];
    __shared__ int   toks[128];
    __shared__ float ws[128];
    __shared__ int   prows[128];
    __shared__ __align__(8) uint64_t s_full[DN_NS], s_empty[DN_NS];

    int tid = threadIdx.x, lane = tid & 31, warp = tid >> 5;
    if (tid == 0) {
#pragma unroll
        for (int s = 0; s < DN_NS; s++) { mbar_init(s2u(&s_full[s]), 256); mbar_init(s2u(&s_empty[s]), 8); }
    }
    if (tid < 128) {
        bool ok = (r0 + tid) < cnt;
        toks[tid]  = ok ? g_tok[e][r0 + tid] : 0;
        ws[tid]    = ok ? g_wt [e][r0 + tid] : 0.f;
        prows[tid] = ok ? (g_base[e] + r0 + tid) : g_base[e];
    }
    __syncthreads();

    uint32_t sbase = s2u(smx);
    uint32_t mbf = s2u(&s_full[0]), mbe = s2u(&s_empty[0]);
    int lr = tid >> 2, kg = tid & 3;

    const char* pi = (const char*)g_iq;
    const char* pd = (const char*)g_dq;

    uint32_t a0 = (uint32_t)prows[lr]      * (DFFC*2) + kg*16;
    uint32_t a1 = (uint32_t)prows[lr + 64] * (DFFC*2) + kg*16;
    uint32_t wofs = (uint32_t)(e * HH + n0) * (DFFC*2);
    uint32_t b0 = wofs + (uint32_t)lr        * (DFFC*2) + kg*16;
    uint32_t b1 = wofs + (uint32_t)(lr + 64) * (DFFC*2) + kg*16;
    uint32_t so0 = lr * 80 + kg * 16;

    auto issue = [&](int kt, int slot) {
        uint32_t sb = sbase + slot * DN_STAGE;
        uint32_t kb = (uint32_t)kt * 64;
        uint32_t sA = sb, sB = sb + DNA_TILE;
        cp16(sA + so0,        pi + a0 + kb); cp16(sA + so0 + 5120, pi + a1 + kb);
        cp16(sB + so0,        pd + b0 + kb); cp16(sB + so0 + 5120, pd + b1 + kb);
    };

    issue(0, 0); cp_arrive(mbf);
    issue(1, 1); cp_arrive(mbf + 8);

    int wm = warp >> 1, wn = warp & 1;
    int m0 = wm * 32, nb = wn * 64;

    float c[2][8][4];
#pragma unroll
    for (int a = 0; a < 2; a++)
#pragma unroll
        for (int b = 0; b < 8; b++)
#pragma unroll
            for (int k = 0; k < 4; k++) c[a][b][k] = 0.f;

    // R13 prefetch consume (measured win for down): it = ks*4 + ng
    auto consume = [&](int slot) {
        uint32_t sb = sbase + slot * DN_STAGE;
        uint32_t sA = sb, sB = sb + DNA_TILE;
        unsigned ac0[4], ac1[4], an0[4], an1[4], f[2][4];
        ldfragA(ac0, sA, m0,      0, lane);
        ldfragA(ac1, sA, m0 + 16, 0, lane);
        ldfragB(f[0], sB, nb, 0, lane);
#pragma unroll
        for (int it = 0; it < 8; it++) {
            int ks = it >> 2, ng = it & 3;
            if (it + 1 < 8) {
                int nit = it + 1;
                ldfragB(f[nit & 1], sB, nb + (nit & 3) * 16, nit >> 2, lane);
            }
            if (it == 1) {
                ldfragA(an0, sA, m0,      1, lane);
                ldfragA(an1, sA, m0 + 16, 1, lane);
            }
            unsigned* fh = f[it & 1];
            if (ks == 0) {
                mma16816(c[0][2*ng],   ac0, fh[0], fh[1]);
                mma16816(c[0][2*ng+1], ac0, fh[2], fh[3]);
                mma16816(c[1][2*ng],   ac1, fh[0], fh[1]);
                mma16816(c[1][2*ng+1], ac1, fh[2], fh[3]);
            } else {
                mma16816(c[0][2*ng],   an0, fh[0], fh[1]);
                mma16816(c[0][2*ng+1], an0, fh[2], fh[3]);
                mma16816(c[1][2*ng],   an1, fh[0], fh[1]);
                mma16816(c[1][2*ng+1], an1, fh[2], fh[3]);
            }
        }
    };

    const int NT = DFFC / 32;   // 64
    uint32_t fullP = 0, emptyP = 0;
    int sc = 0, sp = 2;
    for (int kt = 0; kt < NT; kt++) {
        int nx = kt + 2;
        if (nx < NT) {
            if (nx >= DN_NS) {
                mbar_wait(mbe + sp*8, (emptyP >> sp) & 1);
                emptyP ^= (1u << sp);
            }
            issue(nx, sp);
            cp_arrive(mbf + sp*8);
        }
        mbar_wait(mbf + sc*8, (fullP >> sc) & 1);
        fullP ^= (1u << sc);
        consume(sc);
        if (lane == 0) mbar_arrive(mbe + sc*8);
        sc = (sc == DN_NS-1) ? 0 : sc + 1;
        sp = (sp == DN_NS-1) ? 0 : sp + 1;
    }

    // epilogue: weighted vector-atomic scatter
#pragma unroll
    for (int mi = 0; mi < 2; mi++)
#pragma unroll
        for (int half = 0; half < 2; half++) {
            int rl = m0 + mi*16 + (lane >> 2) + half*8;
            if (r0 + rl < cnt) {
                int   t = toks[rl];
                float w = ws[rl];
                float* dst = out + (size_t)t * HH;
#pragma unroll
                for (int j = 0; j < 8; j++) {
                    int col = n0 + nb + j*8 + (lane & 3)*2;
                    red2(dst + col, w * c[mi][j][half*2+0], w * c[mi][j][half*2+1]);
                }
            }
        }
}

// ---------------- launch ----------------
extern "C" void kernel_launch(void* const* d_in, const int* in_sizes, int n_in,
                              void* d_out, int out_size) {
    const float* x    = (const float*)d_in[0];
    const float* cent = (const float*)d_in[1];
    const float* gw   = (const float*)d_in[2];
    const float* uw   = (const float*)d_in[3];
    const float* dw   = (const float*)d_in[4];
    const float* bias = (const float*)d_in[5];
    float* out = (float*)d_out;

    int write_counts = (out_size >= TT * HH + EE) ? 1 : 0;
    int nconv = 3 * NG4 + NX4;

    cudaFuncSetAttribute(k_gateup_mma, cudaFuncAttributeMaxDynamicSharedMemorySize,
                         GU_NS * GU_STAGE);
    cudaFuncSetAttribute(k_down_mma, cudaFuncAttributeMaxDynamicSharedMemorySize,
                         DN_NS * DN_STAGE);

    k_conv<<<(nconv + 255) / 256, 256>>>((const float4*)gw, (const float4*)uw,
                                         (const float4*)dw, (const float4*)x,
                                         (float4*)out);
    k_router<<<TT / 8, 256>>>(x, cent, bias, out, write_counts);
    k_gateup_mma<<<dim3(DFFC / 64, TT / 128, EE), 256, GU_NS * GU_STAGE>>>();
    k_down_mma  <<<dim3(HH / 128, TT / 128, EE), 256, DN_NS * DN_STAGE>>>(out);
}

// round 17
// speedup vs baseline: 1.0444x; 1.0401x over previous
#include <cuda_runtime.h>
#include <cuda_fp16.h>
#include <math.h>
#include <stdint.h>

#define TT   4096
#define EE   8
#define HH   1024
#define DFFC 2048
#define PP   (TT*2)

// ---------------- device scratch ----------------
__device__ int      g_cnt[EE];
__device__ int      g_base[EE];
__device__ int      g_tok[EE][TT];
__device__ float    g_wt [EE][TT];
__device__ unsigned g_ticket = 0;

__device__ __half g_xq[TT*HH];
__device__ __half g_gq[EE*DFFC*HH];
__device__ __half g_uq[EE*DFFC*HH];
__device__ __half g_dq[EE*HH*DFFC];
__device__ __half g_iq[(size_t)PP*DFFC];

// ---------------- helpers ----------------
__device__ __forceinline__ uint32_t s2u(const void* p) {
    return (uint32_t)__cvta_generic_to_shared(p);
}
__device__ __forceinline__ void cp16(uint32_t dst, const void* src) {
    asm volatile("cp.async.cg.shared.global [%0], [%1], 16;" :: "r"(dst), "l"(src) : "memory");
}
// mbarrier primitives
__device__ __forceinline__ void mbar_init(uint32_t mb, uint32_t cnt) {
    asm volatile("mbarrier.init.shared.b64 [%0], %1;" :: "r"(mb), "r"(cnt) : "memory");
}
// arrive (consuming one expected arrival) once ALL this thread's prior cp.async landed.
// .noinc is ESSENTIAL (R11 hang without it).
__device__ __forceinline__ void cp_arrive(uint32_t mb) {
    asm volatile("cp.async.mbarrier.arrive.noinc.shared.b64 [%0];" :: "r"(mb) : "memory");
}
__device__ __forceinline__ void mbar_arrive(uint32_t mb) {
    asm volatile("mbarrier.arrive.shared.b64 _, [%0];" :: "r"(mb) : "memory");
}
__device__ __forceinline__ void mbar_wait(uint32_t mb, uint32_t parity) {
    asm volatile("{\n\t.reg .pred P;\n\t"
                 "W%=:\n\t"
                 "mbarrier.try_wait.parity.shared.b64 P, [%0], %1;\n\t"
                 "@P bra.uni D%=;\n\t"
                 "bra.uni W%=;\n\t"
                 "D%=:\n\t}"
                 :: "r"(mb), "r"(parity) : "memory");
}

__device__ __forceinline__ void ldsm4(unsigned &r0, unsigned &r1, unsigned &r2, unsigned &r3,
                                      unsigned addr) {
    asm volatile("ldmatrix.sync.aligned.m8n8.x4.shared.b16 {%0,%1,%2,%3}, [%4];"
                 : "=r"(r0), "=r"(r1), "=r"(r2), "=r"(r3) : "r"(addr));
}
__device__ __forceinline__ void mma16816(float c[4], const unsigned a[4],
                                         unsigned b0, unsigned b1) {
    asm volatile("mma.sync.aligned.m16n8k16.row.col.f32.f16.f16.f32 "
                 "{%0,%1,%2,%3}, {%4,%5,%6,%7}, {%8,%9}, {%0,%1,%2,%3};"
                 : "+f"(c[0]), "+f"(c[1]), "+f"(c[2]), "+f"(c[3])
                 : "r"(a[0]), "r"(a[1]), "r"(a[2]), "r"(a[3]), "r"(b0), "r"(b1));
}
// 16x16 A fragment at (m0, k=ks*16), smem tile row stride 80B
__device__ __forceinline__ void ldfragA(unsigned f[4], unsigned base, int m0, int ks, int lane) {
    int sub = lane >> 3;
    int r   = m0 + (lane & 7) + ((sub & 1) << 3);
    int kg  = (ks << 1) + (sub >> 1);
    ldsm4(f[0], f[1], f[2], f[3], base + r * 80 + (kg << 4));
}
// B fragments for 2 adjacent n8 tiles (n0..n0+15) at k=ks*16
__device__ __forceinline__ void ldfragB(unsigned f[4], unsigned base, int n0, int ks, int lane) {
    int sub = lane >> 3;
    int r   = n0 + (lane & 7) + ((sub >> 1) << 3);
    int kg  = (ks << 1) + (sub & 1);
    ldsm4(f[0], f[1], f[2], f[3], base + r * 80 + (kg << 4));
}
__device__ __forceinline__ void red2(float* p, float x, float y) {
    asm volatile("red.global.add.v2.f32 [%0], {%1,%2};" :: "l"(p), "f"(x), "f"(y) : "memory");
}

// ---------------- kernel: convert weights + zero out + reset counters -------
// (x conversion moved into k_router, where the row is already L1/L2 resident)
#define NG4 (EE*DFFC*HH/4)
#define NZ4 (TT*HH/4)
__global__ void k_conv(const float4* __restrict__ gw, const float4* __restrict__ uw,
                       const float4* __restrict__ dw, float4* __restrict__ out) {
    int i = blockIdx.x * blockDim.x + threadIdx.x;
    if (i < EE) g_cnt[i] = 0;
    if (i < NZ4) out[i] = make_float4(0.f, 0.f, 0.f, 0.f);

    const float4* src; __half* dst; int idx;
    if      (i < NG4)   { src = gw; dst = g_gq; idx = i; }
    else if (i < 2*NG4) { src = uw; dst = g_uq; idx = i - NG4; }
    else if (i < 3*NG4) { src = dw; dst = g_dq; idx = i - 2*NG4; }
    else return;

    float4 v = __ldcs(src + idx);
    __stcs((__half2*)dst + 2*idx,     __floats2half2_rn(v.x, v.y));
    __stcs((__half2*)dst + 2*idx + 1, __floats2half2_rn(v.z, v.w));
}

// ---------------- kernel: router (+ x->fp16 + fused prefix/counts) ----------
__global__ void k_router(const float* __restrict__ x, const float* __restrict__ cent,
                         const float* __restrict__ bias,
                         float* __restrict__ out, int write_counts) {
    int warp = threadIdx.x >> 5, lane = threadIdx.x & 31;
    int t = blockIdx.x * 8 + warp;
    const float* xr = x + (size_t)t * HH;
    float acc[EE];
#pragma unroll
    for (int e = 0; e < EE; e++) acc[e] = 0.f;
    for (int h = lane; h < HH; h += 32) {
        float xv = xr[h];
#pragma unroll
        for (int e = 0; e < EE; e++) acc[e] += xv * cent[e * HH + h];
    }

    // convert this token's x row to fp16 (row is hot in L1/L2 from the loop above)
    {
        const float4* xr4 = (const float4*)xr;
        __half2* dst = (__half2*)(g_xq + (size_t)t * HH);
#pragma unroll
        for (int q = lane; q < HH / 4; q += 32) {
            float4 v = xr4[q];
            dst[2*q]     = __floats2half2_rn(v.x, v.y);
            dst[2*q + 1] = __floats2half2_rn(v.z, v.w);
        }
    }

#pragma unroll
    for (int e = 0; e < EE; e++)
#pragma unroll
        for (int o = 16; o > 0; o >>= 1)
            acc[e] += __shfl_down_sync(0xffffffffu, acc[e], o);
    if (lane == 0) {
        float s[EE];
#pragma unroll
        for (int e = 0; e < EE; e++)
            s[e] = 1.f / (1.f + expf(-acc[e])) + bias[e];
        float v0 = -1e30f; int i0 = 0;
#pragma unroll
        for (int e = 0; e < EE; e++) if (s[e] > v0) { v0 = s[e]; i0 = e; }
        float v1 = -1e30f; int i1 = 0;
#pragma unroll
        for (int e = 0; e < EE; e++) if (e != i0 && s[e] > v1) { v1 = s[e]; i1 = e; }
        float e1 = expf(v1 - v0);
        float w0 = 1.f / (1.f + e1), w1 = e1 * w0;
        int s0 = atomicAdd(&g_cnt[i0], 1);
        g_tok[i0][s0] = t; g_wt[i0][s0] = w0;
        int s1 = atomicAdd(&g_cnt[i1], 1);
        g_tok[i1][s1] = t; g_wt[i1][s1] = w1;
    }

    __syncthreads();
    if (threadIdx.x == 0) {
        __threadfence();
        unsigned tk = atomicAdd(&g_ticket, 1);
        if (tk == gridDim.x - 1) {
            g_ticket = 0;
            int b = 0;
#pragma unroll
            for (int e = 0; e < EE; e++) {
                g_base[e] = b;
                int c = g_cnt[e];
                b += c;
                if (write_counts) out[(size_t)TT * HH + e] = (float)c;
            }
        }
    }
}

// ============ gate/up grouped GEMM + fused SwiGLU (R12 consume) ============
// CTA: 64 tokens x 64 dff (gate & up), BK=32, 128 thr, warps 2x2 (m32 n32).
#define GU_TILE  5120                 // 64 rows * 80B
#define GU_STAGE (3*GU_TILE)          // A G U
#define GU_NS    3
__global__ __launch_bounds__(128) void k_gateup_mma() {
    int e   = blockIdx.z;
    int cnt = g_cnt[e];
    int r0  = blockIdx.y * 64;
    if (r0 >= cnt) return;
    int n0  = blockIdx.x * 64;

    extern __shared__ __align__(128) char smx[];
    __shared__ int toks[64];
    __shared__ __align__(8) uint64_t s_full[GU_NS], s_empty[GU_NS];

    int tid = threadIdx.x, lane = tid & 31, warp = tid >> 5;
    if (tid == 0) {
#pragma unroll
        for (int s = 0; s < GU_NS; s++) { mbar_init(s2u(&s_full[s]), 128); mbar_init(s2u(&s_empty[s]), 4); }
    }
    if (tid < 64) toks[tid] = (r0 + tid < cnt) ? g_tok[e][r0 + tid] : g_tok[e][0];
    __syncthreads();

    uint32_t sbase = s2u(smx);
    uint32_t mbf = s2u(&s_full[0]), mbe = s2u(&s_empty[0]);
    int row0 = tid >> 2, kg = tid & 3;

    const char* px = (const char*)g_xq;
    const char* pg = (const char*)g_gq;
    const char* pu = (const char*)g_uq;

    uint32_t a0 = (uint32_t)toks[row0]      * (HH*2) + kg*16;
    uint32_t a1 = (uint32_t)toks[row0 + 32] * (HH*2) + kg*16;
    uint32_t wofs = (uint32_t)(e * DFFC + n0) * (HH*2);
    uint32_t w0 = wofs + (uint32_t)row0        * (HH*2) + kg*16;
    uint32_t w1 = wofs + (uint32_t)(row0 + 32) * (HH*2) + kg*16;
    uint32_t so0 = row0 * 80 + kg * 16, so1 = so0 + 2560;

    auto issue = [&](int kt, int slot) {
        uint32_t sb = sbase + slot * GU_STAGE;
        uint32_t kb = (uint32_t)kt * 64;
        cp16(sb             + so0, px + a0 + kb); cp16(sb             + so1, px + a1 + kb);
        cp16(sb +   GU_TILE + so0, pg + w0 + kb); cp16(sb +   GU_TILE + so1, pg + w1 + kb);
        cp16(sb + 2*GU_TILE + so0, pu + w0 + kb); cp16(sb + 2*GU_TILE + so1, pu + w1 + kb);
    };

    issue(0, 0); cp_arrive(mbf);
    issue(1, 1); cp_arrive(mbf + 8);

    int wm = warp >> 1, wn = warp & 1;
    int m0 = wm * 32, nb = wn * 32;

    float cg[2][4][4], cu[2][4][4];
#pragma unroll
    for (int a = 0; a < 2; a++)
#pragma unroll
        for (int b = 0; b < 4; b++)
#pragma unroll
            for (int c = 0; c < 4; c++) { cg[a][b][c] = 0.f; cu[a][b][c] = 0.f; }

    // R12 simple consume (measured best for gateup; prefetch regressed twice)
    auto consume = [&](int slot) {
        uint32_t sb = sbase + slot * GU_STAGE;
        uint32_t sA = sb, sG = sb + GU_TILE, sU = sb + 2*GU_TILE;
#pragma unroll
        for (int ks = 0; ks < 2; ks++) {
            unsigned ah0[4], ah1[4], fh[4];
            ldfragA(ah0, sA, m0,      ks, lane);
            ldfragA(ah1, sA, m0 + 16, ks, lane);
#pragma unroll
            for (int ng = 0; ng < 2; ng++) {
                ldfragB(fh, sG, nb + ng*16, ks, lane);
                mma16816(cg[0][2*ng],   ah0, fh[0], fh[1]);
                mma16816(cg[0][2*ng+1], ah0, fh[2], fh[3]);
                mma16816(cg[1][2*ng],   ah1, fh[0], fh[1]);
                mma16816(cg[1][2*ng+1], ah1, fh[2], fh[3]);
            }
#pragma unroll
            for (int ng = 0; ng < 2; ng++) {
                ldfragB(fh, sU, nb + ng*16, ks, lane);
                mma16816(cu[0][2*ng],   ah0, fh[0], fh[1]);
                mma16816(cu[0][2*ng+1], ah0, fh[2], fh[3]);
                mma16816(cu[1][2*ng],   ah1, fh[0], fh[1]);
                mma16816(cu[1][2*ng+1], ah1, fh[2], fh[3]);
            }
        }
    };

    const int NT = HH / 32;   // 32
    uint32_t fullP = 0, emptyP = 0;
    int sc = 0, sp = 2;
    for (int kt = 0; kt < NT; kt++) {
        int nx = kt + 2;
        if (nx < NT) {
            if (nx >= GU_NS) {                       // WAR: slot reused
                mbar_wait(mbe + sp*8, (emptyP >> sp) & 1);
                emptyP ^= (1u << sp);
            }
            issue(nx, sp);
            cp_arrive(mbf + sp*8);
        }
        mbar_wait(mbf + sc*8, (fullP >> sc) & 1);    // RAW: stage data ready
        fullP ^= (1u << sc);
        consume(sc);
        if (lane == 0) mbar_arrive(mbe + sc*8);      // per-warp release
        sc = (sc == GU_NS-1) ? 0 : sc + 1;
        sp = (sp == GU_NS-1) ? 0 : sp + 1;
    }

    // epilogue: SwiGLU in fp32 registers (fast exp), store fp16 intermediate
    int pb = g_base[e] + r0;
#pragma unroll
    for (int mi = 0; mi < 2; mi++)
#pragma unroll
        for (int half = 0; half < 2; half++) {
            int rl = m0 + mi*16 + (lane >> 2) + half*8;
            if (r0 + rl < cnt) {
                size_t p = (size_t)(pb + rl);
#pragma unroll
                for (int j = 0; j < 4; j++) {
                    int col = n0 + nb + j*8 + (lane & 3)*2;
                    float g0 = cg[mi][j][half*2+0], g1 = cg[mi][j][half*2+1];
                    float u0 = cu[mi][j][half*2+0], u1 = cu[mi][j][half*2+1];
                    float h0 = (g0 / (1.f + __expf(-g0))) * u0;
                    float h1 = (g1 / (1.f + __expf(-g1))) * u1;
                    *(__half2*)(g_iq + p * DFFC + col) = __floats2half2_rn(h0, h1);
                }
            }
        }
}

// ============ down grouped GEMM + weighted scatter (R13 prefetch consume) ===
// CTA: 64 pairs x 128 H, BK=32, 128 thr. Warp (2x2): m32 x n64. 3-slot ring.
#define DN_ATILE 5120                 // 64 * 80
#define DN_BTILE 10240                // 128 * 80
#define DN_STAGE (DN_ATILE + DN_BTILE)   // 15360
#define DN_NS    3
__global__ __launch_bounds__(128) void k_down_mma(float* __restrict__ out) {
    int e   = blockIdx.z;
    int cnt = g_cnt[e];
    int r0  = blockIdx.y * 64;
    if (r0 >= cnt) return;
    int n0  = blockIdx.x * 128;

    extern __shared__ __align__(128) char smx[];
    __shared__ int   toks[64];
    __shared__ float ws[64];
    __shared__ int   prows[64];
    __shared__ __align__(8) uint64_t s_full[DN_NS], s_empty[DN_NS];

    int tid = threadIdx.x, lane = tid & 31, warp = tid >> 5;
    if (tid == 0) {
#pragma unroll
        for (int s = 0; s < DN_NS; s++) { mbar_init(s2u(&s_full[s]), 128); mbar_init(s2u(&s_empty[s]), 4); }
    }
    if (tid < 64) {
        bool ok = (r0 + tid) < cnt;
        toks[tid]  = ok ? g_tok[e][r0 + tid] : 0;
        ws[tid]    = ok ? g_wt [e][r0 + tid] : 0.f;
        prows[tid] = ok ? (g_base[e] + r0 + tid) : g_base[e];
    }
    __syncthreads();

    uint32_t sbase = s2u(smx);
    uint32_t mbf = s2u(&s_full[0]), mbe = s2u(&s_empty[0]);
    int row0 = tid >> 2, kg = tid & 3;

    const char* pi = (const char*)g_iq;
    const char* pd = (const char*)g_dq;

    uint32_t a0 = (uint32_t)prows[row0]      * (DFFC*2) + kg*16;
    uint32_t a1 = (uint32_t)prows[row0 + 32] * (DFFC*2) + kg*16;
    uint32_t wofs = (uint32_t)(e * HH + n0) * (DFFC*2);
    uint32_t b0 = wofs + (uint32_t)row0        * (DFFC*2) + kg*16;
    uint32_t b1 = wofs + (uint32_t)(row0 + 32) * (DFFC*2) + kg*16;
    uint32_t b2 = wofs + (uint32_t)(row0 + 64) * (DFFC*2) + kg*16;
    uint32_t b3 = wofs + (uint32_t)(row0 + 96) * (DFFC*2) + kg*16;
    uint32_t so0 = row0 * 80 + kg * 16;

    auto issue = [&](int kt, int slot) {
        uint32_t sb = sbase + slot * DN_STAGE;
        uint32_t kb = (uint32_t)kt * 64;
        uint32_t sA = sb, sB = sb + DN_ATILE;
        cp16(sA + so0,        pi + a0 + kb); cp16(sA + so0 + 2560, pi + a1 + kb);
        cp16(sB + so0,        pd + b0 + kb); cp16(sB + so0 + 2560, pd + b1 + kb);
        cp16(sB + so0 + 5120, pd + b2 + kb); cp16(sB + so0 + 7680, pd + b3 + kb);
    };

    issue(0, 0); cp_arrive(mbf);
    issue(1, 1); cp_arrive(mbf + 8);

    int wm = warp >> 1, wn = warp & 1;
    int m0 = wm * 32, nb = wn * 64;

    float c[2][8][4];
#pragma unroll
    for (int a = 0; a < 2; a++)
#pragma unroll
        for (int b = 0; b < 8; b++)
#pragma unroll
            for (int k = 0; k < 4; k++) c[a][b][k] = 0.f;

    // R13 prefetch consume (measured win for down): it = ks*4 + ng
    auto consume = [&](int slot) {
        uint32_t sb = sbase + slot * DN_STAGE;
        uint32_t sA = sb, sB = sb + DN_ATILE;
        unsigned ac0[4], ac1[4], an0[4], an1[4], f[2][4];
        ldfragA(ac0, sA, m0,      0, lane);
        ldfragA(ac1, sA, m0 + 16, 0, lane);
        ldfragB(f[0], sB, nb, 0, lane);
#pragma unroll
        for (int it = 0; it < 8; it++) {
            int ks = it >> 2, ng = it & 3;
            if (it + 1 < 8) {
                int nit = it + 1;
                ldfragB(f[nit & 1], sB, nb + (nit & 3) * 16, nit >> 2, lane);
            }
            if (it == 1) {
                ldfragA(an0, sA, m0,      1, lane);
                ldfragA(an1, sA, m0 + 16, 1, lane);
            }
            unsigned* fh = f[it & 1];
            if (ks == 0) {
                mma16816(c[0][2*ng],   ac0, fh[0], fh[1]);
                mma16816(c[0][2*ng+1], ac0, fh[2], fh[3]);
                mma16816(c[1][2*ng],   ac1, fh[0], fh[1]);
                mma16816(c[1][2*ng+1], ac1, fh[2], fh[3]);
            } else {
                mma16816(c[0][2*ng],   an0, fh[0], fh[1]);
                mma16816(c[0][2*ng+1], an0, fh[2], fh[3]);
                mma16816(c[1][2*ng],   an1, fh[0], fh[1]);
                mma16816(c[1][2*ng+1], an1, fh[2], fh[3]);
            }
        }
    };

    const int NT = DFFC / 32;   // 64
    uint32_t fullP = 0, emptyP = 0;
    int sc = 0, sp = 2;
    for (int kt = 0; kt < NT; kt++) {
        int nx = kt + 2;
        if (nx < NT) {
            if (nx >= DN_NS) {
                mbar_wait(mbe + sp*8, (emptyP >> sp) & 1);
                emptyP ^= (1u << sp);
            }
            issue(nx, sp);
            cp_arrive(mbf + sp*8);
        }
        mbar_wait(mbf + sc*8, (fullP >> sc) & 1);
        fullP ^= (1u << sc);
        consume(sc);
        if (lane == 0) mbar_arrive(mbe + sc*8);
        sc = (sc == DN_NS-1) ? 0 : sc + 1;
        sp = (sp == DN_NS-1) ? 0 : sp + 1;
    }

    // epilogue: weighted vector-atomic scatter
#pragma unroll
    for (int mi = 0; mi < 2; mi++)
#pragma unroll
        for (int half = 0; half < 2; half++) {
            int rl = m0 + mi*16 + (lane >> 2) + half*8;
            if (r0 + rl < cnt) {
                int   t = toks[rl];
                float w = ws[rl];
                float* dst = out + (size_t)t * HH;
#pragma unroll
                for (int j = 0; j < 8; j++) {
                    int col = n0 + nb + j*8 + (lane & 3)*2;
                    red2(dst + col, w * c[mi][j][half*2+0], w * c[mi][j][half*2+1]);
                }
            }
        }
}

// ---------------- launch ----------------
extern "C" void kernel_launch(void* const* d_in, const int* in_sizes, int n_in,
                              void* d_out, int out_size) {
    const float* x    = (const float*)d_in[0];
    const float* cent = (const float*)d_in[1];
    const float* gw   = (const float*)d_in[2];
    const float* uw   = (const float*)d_in[3];
    const float* dw   = (const float*)d_in[4];
    const float* bias = (const float*)d_in[5];
    float* out = (float*)d_out;

    int write_counts = (out_size >= TT * HH + EE) ? 1 : 0;
    int nconv = 3 * NG4;

    cudaFuncSetAttribute(k_gateup_mma, cudaFuncAttributeMaxDynamicSharedMemorySize,
                         GU_NS * GU_STAGE);
    cudaFuncSetAttribute(k_down_mma, cudaFuncAttributeMaxDynamicSharedMemorySize,
                         DN_NS * DN_STAGE);

    k_conv<<<(nconv + 255) / 256, 256>>>((const float4*)gw, (const float4*)uw,
                                         (const float4*)dw, (float4*)out);
    k_router<<<TT / 8, 256>>>(x, cent, bias, out, write_counts);
    k_gateup_mma<<<dim3(DFFC / 64, TT / 64, EE), 128, GU_NS * GU_STAGE>>>();
    k_down_mma  <<<dim3(HH / 128, TT / 64, EE), 128, DN_NS * DN_STAGE>>>(out);
}